// round 11
// baseline (speedup 1.0000x reference)
#include <cuda_runtime.h>
#include <math.h>

#define BN_EPS 1e-5f

typedef unsigned long long ull;

__device__ __forceinline__ ull pk2(float lo, float hi) {
    ull r; asm("mov.b64 %0, {%1, %2};" : "=l"(r) : "f"(lo), "f"(hi)); return r;
}
__device__ __forceinline__ float2 upk2(ull v) {
    float2 f; asm("mov.b64 {%0, %1}, %2;" : "=f"(f.x), "=f"(f.y) : "l"(v)); return f;
}
__device__ __forceinline__ ull ff2(ull a, ull b, ull c) {
    ull d; asm("fma.rn.f32x2 %0, %1, %2, %3;" : "=l"(d) : "l"(a), "l"(b), "l"(c)); return d;
}

// ---------------- scratch (device globals; no allocation allowed) ----------------
__device__ float g_h1[4096 * 32 * 16 * 16];   // 128 MB  [B,32,16,16]
__device__ float g_h2[4096 * 64 * 8 * 8];     //  64 MB  [B,64,8,8]
__device__ float g_feat[4096 * 128];          //   2 MB  [B,128]
__device__ ull   g_pw2[64 * 288];             // conv2 weights, duplicated f32x2
__device__ ull   g_pw3[128 * 576];            // conv3 weights, duplicated f32x2

// =============================================================================
// Prep: duplicate-pack conv2/conv3 weights (w -> (w,w) as ull).
// =============================================================================
__global__ __launch_bounds__(256) void pack_weights(
    const float* __restrict__ w2, const float* __restrict__ w3)
{
    int i = blockIdx.x * 256 + threadIdx.x;
    if (i < 64 * 288) { float v = w2[i]; g_pw2[i] = pk2(v, v); }
    if (i < 128 * 576) { float v = w3[i]; g_pw3[i] = pk2(v, v); }
}

// =============================================================================
// Stage 1: conv(3->32) + BN + ReLU + pool. grid=B, block=128. (unchanged)
// =============================================================================
__global__ __launch_bounds__(128) void conv1_kernel(
    const float* __restrict__ x,
    const float* __restrict__ w,     // [32,3,3,3]
    const float* __restrict__ bias,
    const float* __restrict__ gam,
    const float* __restrict__ bet,
    const float* __restrict__ mean,
    const float* __restrict__ var)
{
    __shared__ float s_in[3][34][36];
    __shared__ float s_w[32 * 27];
    __shared__ float s_scale[32], s_shift[32];
    __shared__ float s_stg[32][34];

    const int b = blockIdx.x;
    const int tid = threadIdx.x;
    const float* xb = x + (size_t)b * 3 * 32 * 32;

    for (int i = tid; i < 3 * 34 * 36; i += 128) {
        int c = i % 36;
        int r = (i / 36) % 34;
        int ch = i / (36 * 34);
        float v = 0.f;
        if (r >= 1 && r <= 32 && c >= 1 && c <= 32)
            v = xb[ch * 1024 + (r - 1) * 32 + (c - 1)];
        s_in[ch][r][c] = v;
    }
    for (int i = tid; i < 32 * 27; i += 128) s_w[i] = w[i];
    if (tid < 32) {
        float inv = gam[tid] * rsqrtf(var[tid] + BN_EPS);
        s_scale[tid] = inv;
        s_shift[tid] = (bias[tid] - mean[tid]) * inv + bet[tid];
    }
    __syncthreads();

    const int ocp = tid & 15;
    const int oc0 = ocp * 2;
    const int slot = tid >> 4;
    float* ob = g_h1 + (size_t)b * 8192;

    for (int rep = 0; rep < 8; rep++) {
        int combo = rep * 8 + slot;
        int py = combo >> 2;
        int q = combo & 3;
        int r0 = 2 * py;
        int x0 = q * 8;

        ull acc[2][8];
        #pragma unroll
        for (int i = 0; i < 8; i++) { acc[0][i] = 0ull; acc[1][i] = 0ull; }

        #pragma unroll
        for (int ic = 0; ic < 3; ic++) {
            const float* wq0 = &s_w[oc0 * 27 + ic * 9];
            const float* wq1 = wq0 + 27;
            ull wp0[9], wp1[9];
            #pragma unroll
            for (int k = 0; k < 9; k++) {
                float a = wq0[k], c_ = wq1[k];
                wp0[k] = pk2(a, a);
                wp1[k] = pk2(c_, c_);
            }
            float v0, v1, v2, v3;
            v0 = s_in[ic][r0][x0];     v1 = s_in[ic][r0 + 1][x0];
            v2 = s_in[ic][r0 + 2][x0]; v3 = s_in[ic][r0 + 3][x0];
            ull X0 = pk2(v0, v1), Y0 = pk2(v1, v2), Z0 = pk2(v2, v3);
            v0 = s_in[ic][r0][x0 + 1];     v1 = s_in[ic][r0 + 1][x0 + 1];
            v2 = s_in[ic][r0 + 2][x0 + 1]; v3 = s_in[ic][r0 + 3][x0 + 1];
            ull X1 = pk2(v0, v1), Y1 = pk2(v1, v2), Z1 = pk2(v2, v3);

            #pragma unroll
            for (int cx = 0; cx < 8; cx++) {
                int c = x0 + cx + 2;
                v0 = s_in[ic][r0][c];     v1 = s_in[ic][r0 + 1][c];
                v2 = s_in[ic][r0 + 2][c]; v3 = s_in[ic][r0 + 3][c];
                ull X2 = pk2(v0, v1), Y2 = pk2(v1, v2), Z2 = pk2(v2, v3);
                ull t = acc[0][cx];
                t = ff2(wp0[0], X0, t); t = ff2(wp0[1], X1, t); t = ff2(wp0[2], X2, t);
                t = ff2(wp0[3], Y0, t); t = ff2(wp0[4], Y1, t); t = ff2(wp0[5], Y2, t);
                t = ff2(wp0[6], Z0, t); t = ff2(wp0[7], Z1, t); t = ff2(wp0[8], Z2, t);
                acc[0][cx] = t;
                ull u = acc[1][cx];
                u = ff2(wp1[0], X0, u); u = ff2(wp1[1], X1, u); u = ff2(wp1[2], X2, u);
                u = ff2(wp1[3], Y0, u); u = ff2(wp1[4], Y1, u); u = ff2(wp1[5], Y2, u);
                u = ff2(wp1[6], Z0, u); u = ff2(wp1[7], Z1, u); u = ff2(wp1[8], Z2, u);
                acc[1][cx] = u;
                X0 = X1; X1 = X2; Y0 = Y1; Y1 = Y2; Z0 = Z1; Z1 = Z2;
            }
        }

        __syncthreads();
        #pragma unroll
        for (int k = 0; k < 2; k++) {
            int oc = oc0 + k;
            float sc = s_scale[oc], sh = s_shift[oc];
            #pragma unroll
            for (int px = 0; px < 4; px++) {
                float2 pa = upk2(acc[k][2 * px]);
                float2 pb = upk2(acc[k][2 * px + 1]);
                float v00 = fmaxf(fmaf(pa.x, sc, sh), 0.f);
                float v10 = fmaxf(fmaf(pa.y, sc, sh), 0.f);
                float v01 = fmaxf(fmaf(pb.x, sc, sh), 0.f);
                float v11 = fmaxf(fmaf(pb.y, sc, sh), 0.f);
                s_stg[oc][(py & 1) * 16 + q * 4 + px] =
                    fmaxf(fmaxf(v00, v01), fmaxf(v10, v11));
            }
        }
        __syncthreads();
        for (int i = tid; i < 1024; i += 128) {
            int oc = i >> 5, pos = i & 31;
            ob[oc * 256 + (rep * 2 + (pos >> 4)) * 16 + (pos & 15)] = s_stg[oc][pos];
        }
    }
}

// =============================================================================
// Stage 2: conv(32->64) + BN + ReLU + pool. grid=B*4, block=128 (4 warps).
// Warp: half h (rows) x oc-set; lane = ocg(4) x cp(8); 2 oc/thread.
// Input rows dual-copy: copyA [0,v0..v15,0] at +0, copyB [v0..v15] at +20,
// row stride 40 -> L,V,R all aligned LDS.64, zero packs. Weights via LDG.64
// from pre-duplicated g_pw2 (L2-resident, lane-broadcast). 4 passes x 8 ic.
// =============================================================================
__global__ __launch_bounds__(128) void conv2_kernel(
    const float* __restrict__ bias,
    const float* __restrict__ gam,
    const float* __restrict__ bet,
    const float* __restrict__ mean,
    const float* __restrict__ var)
{
    __shared__ float s_in[8 * 16 * 40];   // 20 KB

    const int b = blockIdx.x >> 2;
    const int oc_base = (blockIdx.x & 3) * 16;
    const int tid = threadIdx.x;
    const int warp = tid >> 5;
    const int lane = tid & 31;
    const int cp = lane & 7;             // col pair 0..7
    const int ocg = lane >> 3;           // 0..3
    const int h = warp >> 1;             // row half
    const int st = warp & 1;             // oc set
    const int oc0 = oc_base + st * 8 + ocg * 2;

    // static borders (never overwritten by staging)
    {
        int ic = tid >> 4, r = tid & 15;
        s_in[ic * 640 + r * 40] = 0.f;
        s_in[ic * 640 + r * 40 + 17] = 0.f;
    }

    ull acc0[8], acc1[8];
    #pragma unroll
    for (int i = 0; i < 8; i++) { acc0[i] = 0ull; acc1[i] = 0ull; }

    for (int pass = 0; pass < 4; pass++) {
        __syncthreads();
        {
            const float4* src = (const float4*)(g_h1 + (size_t)b * 8192 + pass * 2048);
            #pragma unroll
            for (int i = 0; i < 4; i++) {
                int idx4 = tid + i * 128;          // 0..511
                float4 v = src[idx4];
                int ic = idx4 >> 6;
                int r = (idx4 >> 2) & 15;
                int c4 = (idx4 & 3) * 4;
                float* row = &s_in[ic * 640 + r * 40];
                row[1 + c4] = v.x; row[2 + c4] = v.y;
                row[3 + c4] = v.z; row[4 + c4] = v.w;
                *(float4*)(row + 20 + c4) = v;
            }
        }
        __syncthreads();

        #pragma unroll 1
        for (int ici = 0; ici < 8; ici++) {
            const int ic = pass * 8 + ici;
            const ull* w0p = g_pw2 + oc0 * 288 + ic * 9;
            const ull* w1p = w0p + 288;
            ull W0[9], W1[9];
            #pragma unroll
            for (int k = 0; k < 9; k++) { W0[k] = w0p[k]; W1[k] = w1p[k]; }

            const float* rb = &s_in[ici * 640 + 2 * cp];
            if (h == 0) {
                #pragma unroll
                for (int r = 0; r < 9; r++) {
                    ull L = *(const ull*)(rb + r * 40);
                    ull R = *(const ull*)(rb + r * 40 + 2);
                    ull V = *(const ull*)(rb + r * 40 + 20);
                    if (r >= 1) {
                        acc0[r - 1] = ff2(W0[6], L, ff2(W0[7], V, ff2(W0[8], R, acc0[r - 1])));
                        acc1[r - 1] = ff2(W1[6], L, ff2(W1[7], V, ff2(W1[8], R, acc1[r - 1])));
                    }
                    if (r <= 7) {
                        acc0[r] = ff2(W0[3], L, ff2(W0[4], V, ff2(W0[5], R, acc0[r])));
                        acc1[r] = ff2(W1[3], L, ff2(W1[4], V, ff2(W1[5], R, acc1[r])));
                    }
                    if (r <= 6) {
                        acc0[r + 1] = ff2(W0[0], L, ff2(W0[1], V, ff2(W0[2], R, acc0[r + 1])));
                        acc1[r + 1] = ff2(W1[0], L, ff2(W1[1], V, ff2(W1[2], R, acc1[r + 1])));
                    }
                }
            } else {
                #pragma unroll
                for (int ri = 0; ri < 9; ri++) {
                    const int r = 7 + ri;          // global in row
                    const int t = ri - 1;          // local out base
                    ull L = *(const ull*)(rb + r * 40);
                    ull R = *(const ull*)(rb + r * 40 + 2);
                    ull V = *(const ull*)(rb + r * 40 + 20);
                    if (t >= 1) {
                        acc0[t - 1] = ff2(W0[6], L, ff2(W0[7], V, ff2(W0[8], R, acc0[t - 1])));
                        acc1[t - 1] = ff2(W1[6], L, ff2(W1[7], V, ff2(W1[8], R, acc1[t - 1])));
                    }
                    if (t >= 0 && t <= 7) {
                        acc0[t] = ff2(W0[3], L, ff2(W0[4], V, ff2(W0[5], R, acc0[t])));
                        acc1[t] = ff2(W1[3], L, ff2(W1[4], V, ff2(W1[5], R, acc1[t])));
                    }
                    if (t <= 6) {
                        acc0[t + 1] = ff2(W0[0], L, ff2(W0[1], V, ff2(W0[2], R, acc0[t + 1])));
                        acc1[t + 1] = ff2(W1[0], L, ff2(W1[1], V, ff2(W1[2], R, acc1[t + 1])));
                    }
                }
            }
        }
    }

    // BN + ReLU + 2x2 pool; local pooled rows 0..3 -> global h*4+j, col = cp
    #pragma unroll
    for (int k = 0; k < 2; k++) {
        const int oc = oc0 + k;
        const ull* ac = k ? acc1 : acc0;
        float inv = gam[oc] * rsqrtf(var[oc] + BN_EPS);
        float sh = (bias[oc] - mean[oc]) * inv + bet[oc];
        float* ob = g_h2 + (size_t)b * 4096 + (size_t)oc * 64 + cp;
        #pragma unroll
        for (int j = 0; j < 4; j++) {
            float2 a = upk2(ac[2 * j]);
            float2 c = upk2(ac[2 * j + 1]);
            float v00 = fmaxf(fmaf(a.x, inv, sh), 0.f);
            float v01 = fmaxf(fmaf(a.y, inv, sh), 0.f);
            float v10 = fmaxf(fmaf(c.x, inv, sh), 0.f);
            float v11 = fmaxf(fmaf(c.y, inv, sh), 0.f);
            ob[(h * 4 + j) * 8] = fmaxf(fmaxf(v00, v01), fmaxf(v10, v11));
        }
    }
}

// =============================================================================
// Stage 3: conv(64->128) + BN + ReLU + pool + avgpool. grid=B*2, block=128
// (4 warps x 16 oc). Lane = ocg(8) x cp(4); 2 oc/thread, all 8 rows.
// Input dual-copy rows: copyA [0,v0..v7,0] at +0, copyB [v0..v7] at +12,
// stride 20. Weights via LDG.64 from g_pw3. 2 input passes x 32 ic; no
// weight staging, no cross-warp reduction.
// =============================================================================
__global__ __launch_bounds__(128) void conv3_kernel(
    const float* __restrict__ bias,
    const float* __restrict__ gam,
    const float* __restrict__ bet,
    const float* __restrict__ mean,
    const float* __restrict__ var)
{
    __shared__ float s_in[32 * 160];   // 32 ic x 8 rows x 20 = 20 KB

    const int b = blockIdx.x >> 1;
    const int oc_base = (blockIdx.x & 1) * 64;
    const int tid = threadIdx.x;
    const int warp = tid >> 5;
    const int lane = tid & 31;
    const int cp = lane & 3;             // col pair 0..3
    const int ocg = lane >> 2;           // 0..7
    const int oc0 = oc_base + warp * 16 + ocg * 2;

    // static borders
    for (int i = tid; i < 256; i += 128) {
        int ic = i >> 3, r = i & 7;
        s_in[ic * 160 + r * 20] = 0.f;
        s_in[ic * 160 + r * 20 + 9] = 0.f;
    }

    ull acc0[8], acc1[8];
    #pragma unroll
    for (int i = 0; i < 8; i++) { acc0[i] = 0ull; acc1[i] = 0ull; }

    for (int pass = 0; pass < 2; pass++) {
        __syncthreads();
        {
            const float4* src = (const float4*)(g_h2 + (size_t)b * 4096 + pass * 2048);
            #pragma unroll
            for (int i = 0; i < 4; i++) {
                int idx4 = tid + i * 128;           // 0..511
                float4 v = src[idx4];
                int ic = idx4 >> 4;
                int r = (idx4 >> 1) & 7;
                int c4 = (idx4 & 1) * 4;
                float* row = &s_in[ic * 160 + r * 20];
                row[1 + c4] = v.x; row[2 + c4] = v.y;
                row[3 + c4] = v.z; row[4 + c4] = v.w;
                *(float4*)(row + 12 + c4) = v;
            }
        }
        __syncthreads();

        #pragma unroll 1
        for (int ici = 0; ici < 32; ici++) {
            const int ic = pass * 32 + ici;
            const ull* w0p = g_pw3 + oc0 * 576 + ic * 9;
            const ull* w1p = w0p + 576;
            ull W0[9], W1[9];
            #pragma unroll
            for (int k = 0; k < 9; k++) { W0[k] = w0p[k]; W1[k] = w1p[k]; }

            const float* rb = &s_in[ici * 160 + 2 * cp];
            #pragma unroll
            for (int r = 0; r < 8; r++) {
                ull L = *(const ull*)(rb + r * 20);
                ull R = *(const ull*)(rb + r * 20 + 2);
                ull V = *(const ull*)(rb + r * 20 + 12);
                if (r >= 1) {
                    acc0[r - 1] = ff2(W0[6], L, ff2(W0[7], V, ff2(W0[8], R, acc0[r - 1])));
                    acc1[r - 1] = ff2(W1[6], L, ff2(W1[7], V, ff2(W1[8], R, acc1[r - 1])));
                }
                acc0[r] = ff2(W0[3], L, ff2(W0[4], V, ff2(W0[5], R, acc0[r])));
                acc1[r] = ff2(W1[3], L, ff2(W1[4], V, ff2(W1[5], R, acc1[r])));
                if (r <= 6) {
                    acc0[r + 1] = ff2(W0[0], L, ff2(W0[1], V, ff2(W0[2], R, acc0[r + 1])));
                    acc1[r + 1] = ff2(W1[0], L, ff2(W1[1], V, ff2(W1[2], R, acc1[r + 1])));
                }
            }
        }
    }

    // BN + ReLU + 2x2 pool + avg: thread holds 4 pooled rows x 1 pooled col (=cp)
    #pragma unroll
    for (int k = 0; k < 2; k++) {
        const int oc = oc0 + k;
        const ull* ac = k ? acc1 : acc0;
        float inv = gam[oc] * rsqrtf(var[oc] + BN_EPS);
        float sh = (bias[oc] - mean[oc]) * inv + bet[oc];
        float sum = 0.f;
        #pragma unroll
        for (int j = 0; j < 4; j++) {
            float2 a = upk2(ac[2 * j]);
            float2 c = upk2(ac[2 * j + 1]);
            float v00 = fmaxf(fmaf(a.x, inv, sh), 0.f);
            float v01 = fmaxf(fmaf(a.y, inv, sh), 0.f);
            float v10 = fmaxf(fmaf(c.x, inv, sh), 0.f);
            float v11 = fmaxf(fmaf(c.y, inv, sh), 0.f);
            sum += fmaxf(fmaxf(v00, v01), fmaxf(v10, v11));
        }
        sum += __shfl_down_sync(0xffffffffu, sum, 2, 4);
        sum += __shfl_down_sync(0xffffffffu, sum, 1, 4);
        if (cp == 0)
            g_feat[(size_t)b * 128 + oc] = sum * (1.f / 16.f);
    }
}

// =============================================================================
// Stage 4: gate (top-2 softmax) + top-2 expert MLPs, fused. (unchanged, 55us)
// =============================================================================
__global__ __launch_bounds__(256) void moe_kernel(
    const float* __restrict__ w1,   // [8,128,64]
    const float* __restrict__ b1,   // [8,64]
    const float* __restrict__ w2,   // [8,64,10]
    const float* __restrict__ b2,   // [8,10]
    const float* __restrict__ gw,   // [128,8]
    const float* __restrict__ gb,   // [8]
    float* __restrict__ out, int B)
{
    __shared__ float s_feat[8][128];
    __shared__ float s_h[8][64];
    __shared__ float s_log[8][8];

    const int warp = threadIdx.x >> 5;
    const int lane = threadIdx.x & 31;
    const int s = blockIdx.x * 8 + warp;
    if (s >= B) return;

    for (int i = lane; i < 128; i += 32) s_feat[warp][i] = g_feat[(size_t)s * 128 + i];
    __syncwarp();

    if (lane < 8) {
        float a = gb[lane];
        for (int f = 0; f < 128; f++) a += s_feat[warp][f] * gw[f * 8 + lane];
        s_log[warp][lane] = a;
    }
    __syncwarp();

    float lg[8];
    #pragma unroll
    for (int e = 0; e < 8; e++) lg[e] = s_log[warp][e];
    int i0 = 0; float v0 = lg[0];
    #pragma unroll
    for (int e = 1; e < 8; e++) if (lg[e] > v0) { v0 = lg[e]; i0 = e; }
    int i1 = -1; float v1 = -3.402823466e38f;
    #pragma unroll
    for (int e = 0; e < 8; e++) if (e != i0 && lg[e] > v1) { v1 = lg[e]; i1 = e; }
    float e1 = expf(v1 - v0);
    float invs = 1.f / (1.f + e1);
    float wts[2] = { invs, e1 * invs };
    int eidx[2] = { i0, i1 };

    float outk = 0.f;
    for (int t = 0; t < 2; t++) {
        const int e = eidx[t];
        const float* w1e = w1 + (size_t)e * 128 * 64;
        float h0 = b1[e * 64 + lane];
        float h1v = b1[e * 64 + lane + 32];
        for (int f = 0; f < 128; f++) {
            float fv = s_feat[warp][f];
            h0  += fv * w1e[f * 64 + lane];
            h1v += fv * w1e[f * 64 + lane + 32];
        }
        s_h[warp][lane] = fmaxf(h0, 0.f);
        s_h[warp][lane + 32] = fmaxf(h1v, 0.f);
        __syncwarp();
        if (lane < 10) {
            const float* w2e = w2 + e * 640;
            float o = b2[e * 10 + lane];
            for (int j = 0; j < 64; j++) o += s_h[warp][j] * w2e[j * 10 + lane];
            outk += wts[t] * o;
        }
        __syncwarp();
    }
    if (lane < 10) out[(size_t)s * 10 + lane] = outk;
}

// =============================================================================
extern "C" void kernel_launch(void* const* d_in, const int* in_sizes, int n_in,
                              void* d_out, int out_size)
{
    const float* x       = (const float*)d_in[0];
    const float* c1w     = (const float*)d_in[1];
    const float* c1b     = (const float*)d_in[2];
    const float* bn1g    = (const float*)d_in[3];
    const float* bn1b    = (const float*)d_in[4];
    const float* bn1m    = (const float*)d_in[5];
    const float* bn1v    = (const float*)d_in[6];
    const float* c2w     = (const float*)d_in[7];
    const float* c2b     = (const float*)d_in[8];
    const float* bn2g    = (const float*)d_in[9];
    const float* bn2b    = (const float*)d_in[10];
    const float* bn2m    = (const float*)d_in[11];
    const float* bn2v    = (const float*)d_in[12];
    const float* c3w     = (const float*)d_in[13];
    const float* c3b     = (const float*)d_in[14];
    const float* bn3g    = (const float*)d_in[15];
    const float* bn3b    = (const float*)d_in[16];
    const float* bn3m    = (const float*)d_in[17];
    const float* bn3v    = (const float*)d_in[18];
    const float* w1      = (const float*)d_in[19];
    const float* b1      = (const float*)d_in[20];
    const float* w2      = (const float*)d_in[21];
    const float* b2      = (const float*)d_in[22];
    const float* gate_w  = (const float*)d_in[23];
    const float* gate_b  = (const float*)d_in[24];

    int B = in_sizes[0] / (3 * 32 * 32);
    if (B > 4096) B = 4096;

    // pack kernel doubles as launch-slot shifter: 4th launch (profiled) = conv3
    pack_weights<<<288, 256>>>(c2w, c3w);
    conv1_kernel<<<B, 128>>>(x, c1w, c1b, bn1g, bn1b, bn1m, bn1v);
    conv2_kernel<<<B * 4, 128>>>(c2b, bn2g, bn2b, bn2m, bn2v);
    conv3_kernel<<<B * 2, 128>>>(c3b, bn3g, bn3b, bn3m, bn3v);
    moe_kernel<<<(B + 7) / 8, 256>>>(w1, b1, w2, b2, gate_w, gate_b, (float*)d_out, B);
}

// round 12
// speedup vs baseline: 1.3453x; 1.3453x over previous
#include <cuda_runtime.h>
#include <math.h>

#define BN_EPS 1e-5f

typedef unsigned long long ull;

__device__ __forceinline__ ull pk2(float lo, float hi) {
    ull r; asm("mov.b64 %0, {%1, %2};" : "=l"(r) : "f"(lo), "f"(hi)); return r;
}
__device__ __forceinline__ float2 upk2(ull v) {
    float2 f; asm("mov.b64 {%0, %1}, %2;" : "=f"(f.x), "=f"(f.y) : "l"(v)); return f;
}
__device__ __forceinline__ ull ff2(ull a, ull b, ull c) {
    ull d; asm("fma.rn.f32x2 %0, %1, %2, %3;" : "=l"(d) : "l"(a), "l"(b), "l"(c)); return d;
}

// ---------------- scratch (device globals; no allocation allowed) ----------------
__device__ float g_h1[4096 * 32 * 16 * 16];   // 128 MB  [B,32,16,16]
__device__ float g_h2[4096 * 64 * 8 * 8];     //  64 MB  [B,64,8,8]
__device__ float g_feat[4096 * 128];          //   2 MB  [B,128]
__device__ ull   g_pw2[64 * 288];             // conv2 weights, duplicated f32x2
__device__ ull   g_pw3[128 * 576];            // conv3 weights, duplicated f32x2

// =============================================================================
// Prep: duplicate-pack conv2/conv3 weights (w -> (w,w) as ull).
// =============================================================================
__global__ __launch_bounds__(256) void pack_weights(
    const float* __restrict__ w2, const float* __restrict__ w3)
{
    int i = blockIdx.x * 256 + threadIdx.x;
    if (i < 64 * 288) { float v = w2[i]; g_pw2[i] = pk2(v, v); }
    if (i < 128 * 576) { float v = w3[i]; g_pw3[i] = pk2(v, v); }
}

// =============================================================================
// Stage 1: conv(3->32) + BN + ReLU + pool. grid=B, block=128. (unchanged)
// =============================================================================
__global__ __launch_bounds__(128) void conv1_kernel(
    const float* __restrict__ x,
    const float* __restrict__ w,     // [32,3,3,3]
    const float* __restrict__ bias,
    const float* __restrict__ gam,
    const float* __restrict__ bet,
    const float* __restrict__ mean,
    const float* __restrict__ var)
{
    __shared__ float s_in[3][34][36];
    __shared__ float s_w[32 * 27];
    __shared__ float s_scale[32], s_shift[32];
    __shared__ float s_stg[32][34];

    const int b = blockIdx.x;
    const int tid = threadIdx.x;
    const float* xb = x + (size_t)b * 3 * 32 * 32;

    for (int i = tid; i < 3 * 34 * 36; i += 128) {
        int c = i % 36;
        int r = (i / 36) % 34;
        int ch = i / (36 * 34);
        float v = 0.f;
        if (r >= 1 && r <= 32 && c >= 1 && c <= 32)
            v = xb[ch * 1024 + (r - 1) * 32 + (c - 1)];
        s_in[ch][r][c] = v;
    }
    for (int i = tid; i < 32 * 27; i += 128) s_w[i] = w[i];
    if (tid < 32) {
        float inv = gam[tid] * rsqrtf(var[tid] + BN_EPS);
        s_scale[tid] = inv;
        s_shift[tid] = (bias[tid] - mean[tid]) * inv + bet[tid];
    }
    __syncthreads();

    const int ocp = tid & 15;
    const int oc0 = ocp * 2;
    const int slot = tid >> 4;
    float* ob = g_h1 + (size_t)b * 8192;

    for (int rep = 0; rep < 8; rep++) {
        int combo = rep * 8 + slot;
        int py = combo >> 2;
        int q = combo & 3;
        int r0 = 2 * py;
        int x0 = q * 8;

        ull acc[2][8];
        #pragma unroll
        for (int i = 0; i < 8; i++) { acc[0][i] = 0ull; acc[1][i] = 0ull; }

        #pragma unroll
        for (int ic = 0; ic < 3; ic++) {
            const float* wq0 = &s_w[oc0 * 27 + ic * 9];
            const float* wq1 = wq0 + 27;
            ull wp0[9], wp1[9];
            #pragma unroll
            for (int k = 0; k < 9; k++) {
                float a = wq0[k], c_ = wq1[k];
                wp0[k] = pk2(a, a);
                wp1[k] = pk2(c_, c_);
            }
            float v0, v1, v2, v3;
            v0 = s_in[ic][r0][x0];     v1 = s_in[ic][r0 + 1][x0];
            v2 = s_in[ic][r0 + 2][x0]; v3 = s_in[ic][r0 + 3][x0];
            ull X0 = pk2(v0, v1), Y0 = pk2(v1, v2), Z0 = pk2(v2, v3);
            v0 = s_in[ic][r0][x0 + 1];     v1 = s_in[ic][r0 + 1][x0 + 1];
            v2 = s_in[ic][r0 + 2][x0 + 1]; v3 = s_in[ic][r0 + 3][x0 + 1];
            ull X1 = pk2(v0, v1), Y1 = pk2(v1, v2), Z1 = pk2(v2, v3);

            #pragma unroll
            for (int cx = 0; cx < 8; cx++) {
                int c = x0 + cx + 2;
                v0 = s_in[ic][r0][c];     v1 = s_in[ic][r0 + 1][c];
                v2 = s_in[ic][r0 + 2][c]; v3 = s_in[ic][r0 + 3][c];
                ull X2 = pk2(v0, v1), Y2 = pk2(v1, v2), Z2 = pk2(v2, v3);
                ull t = acc[0][cx];
                t = ff2(wp0[0], X0, t); t = ff2(wp0[1], X1, t); t = ff2(wp0[2], X2, t);
                t = ff2(wp0[3], Y0, t); t = ff2(wp0[4], Y1, t); t = ff2(wp0[5], Y2, t);
                t = ff2(wp0[6], Z0, t); t = ff2(wp0[7], Z1, t); t = ff2(wp0[8], Z2, t);
                acc[0][cx] = t;
                ull u = acc[1][cx];
                u = ff2(wp1[0], X0, u); u = ff2(wp1[1], X1, u); u = ff2(wp1[2], X2, u);
                u = ff2(wp1[3], Y0, u); u = ff2(wp1[4], Y1, u); u = ff2(wp1[5], Y2, u);
                u = ff2(wp1[6], Z0, u); u = ff2(wp1[7], Z1, u); u = ff2(wp1[8], Z2, u);
                acc[1][cx] = u;
                X0 = X1; X1 = X2; Y0 = Y1; Y1 = Y2; Z0 = Z1; Z1 = Z2;
            }
        }

        __syncthreads();
        #pragma unroll
        for (int k = 0; k < 2; k++) {
            int oc = oc0 + k;
            float sc = s_scale[oc], sh = s_shift[oc];
            #pragma unroll
            for (int px = 0; px < 4; px++) {
                float2 pa = upk2(acc[k][2 * px]);
                float2 pb = upk2(acc[k][2 * px + 1]);
                float v00 = fmaxf(fmaf(pa.x, sc, sh), 0.f);
                float v10 = fmaxf(fmaf(pa.y, sc, sh), 0.f);
                float v01 = fmaxf(fmaf(pb.x, sc, sh), 0.f);
                float v11 = fmaxf(fmaf(pb.y, sc, sh), 0.f);
                s_stg[oc][(py & 1) * 16 + q * 4 + px] =
                    fmaxf(fmaxf(v00, v01), fmaxf(v10, v11));
            }
        }
        __syncthreads();
        for (int i = tid; i < 1024; i += 128) {
            int oc = i >> 5, pos = i & 31;
            ob[oc * 256 + (rep * 2 + (pos >> 4)) * 16 + (pos & 15)] = s_stg[oc][pos];
        }
    }
}

// =============================================================================
// Stage 2: conv(32->64) + BN + ReLU + pool. grid=B*4, block=128 (4 warps).
// Warp: half h (rows) x oc-set; lane = ocg(4) x cp(8); 2 oc/thread.
// Input rows dual-copy (stride 40): L,V,R aligned LDS.64, zero packs.
// Packed weights staged into smem per 8-ic pass (stride 73 ull, bank-clean);
// mainloop weights = broadcast LDS.64, zero MOVs, zero LDG.
// =============================================================================
__global__ __launch_bounds__(128) void conv2_kernel(
    const float* __restrict__ bias,
    const float* __restrict__ gam,
    const float* __restrict__ bet,
    const float* __restrict__ mean,
    const float* __restrict__ var)
{
    __shared__ float s_in[8 * 16 * 40];   // 20 KB
    __shared__ ull   s_w[16 * 73];        // 9.3 KB (stride 73: bank-clean)

    const int b = blockIdx.x >> 2;
    const int oc_base = (blockIdx.x & 3) * 16;
    const int tid = threadIdx.x;
    const int warp = tid >> 5;
    const int lane = tid & 31;
    const int cp = lane & 7;             // col pair 0..7
    const int ocg = lane >> 3;           // 0..3
    const int h = warp >> 1;             // row half
    const int st = warp & 1;             // oc set
    const int oc0l = st * 8 + ocg * 2;   // local oc pair base 0..14
    const int oc0 = oc_base + oc0l;

    // static borders (never overwritten by staging)
    {
        int ic = tid >> 4, r = tid & 15;
        s_in[ic * 640 + r * 40] = 0.f;
        s_in[ic * 640 + r * 40 + 17] = 0.f;
    }

    ull acc0[8], acc1[8];
    #pragma unroll
    for (int i = 0; i < 8; i++) { acc0[i] = 0ull; acc1[i] = 0ull; }

    for (int pass = 0; pass < 4; pass++) {
        __syncthreads();
        {
            const float4* src = (const float4*)(g_h1 + (size_t)b * 8192 + pass * 2048);
            #pragma unroll
            for (int i = 0; i < 4; i++) {
                int idx4 = tid + i * 128;          // 0..511
                float4 v = src[idx4];
                int ic = idx4 >> 6;
                int r = (idx4 >> 2) & 15;
                int c4 = (idx4 & 3) * 4;
                float* row = &s_in[ic * 640 + r * 40];
                row[1 + c4] = v.x; row[2 + c4] = v.y;
                row[3 + c4] = v.z; row[4 + c4] = v.w;
                *(float4*)(row + 20 + c4) = v;
            }
        }
        // stage packed weights for this pass: 16 oc x 72 ull
        for (int i = tid; i < 16 * 72; i += 128) {
            int o = i / 72, j = i % 72;
            s_w[o * 73 + j] = g_pw2[(oc_base + o) * 288 + pass * 72 + j];
        }
        __syncthreads();

        #pragma unroll 1
        for (int ici = 0; ici < 8; ici++) {
            const ull* w0p = &s_w[oc0l * 73 + ici * 9];
            const ull* w1p = w0p + 73;
            ull W0[9], W1[9];
            #pragma unroll
            for (int k = 0; k < 9; k++) { W0[k] = w0p[k]; W1[k] = w1p[k]; }

            const float* rb = &s_in[ici * 640 + 2 * cp];
            if (h == 0) {
                #pragma unroll
                for (int r = 0; r < 9; r++) {
                    ull L = *(const ull*)(rb + r * 40);
                    ull R = *(const ull*)(rb + r * 40 + 2);
                    ull V = *(const ull*)(rb + r * 40 + 20);
                    if (r >= 1) {
                        acc0[r - 1] = ff2(W0[6], L, ff2(W0[7], V, ff2(W0[8], R, acc0[r - 1])));
                        acc1[r - 1] = ff2(W1[6], L, ff2(W1[7], V, ff2(W1[8], R, acc1[r - 1])));
                    }
                    if (r <= 7) {
                        acc0[r] = ff2(W0[3], L, ff2(W0[4], V, ff2(W0[5], R, acc0[r])));
                        acc1[r] = ff2(W1[3], L, ff2(W1[4], V, ff2(W1[5], R, acc1[r])));
                    }
                    if (r <= 6) {
                        acc0[r + 1] = ff2(W0[0], L, ff2(W0[1], V, ff2(W0[2], R, acc0[r + 1])));
                        acc1[r + 1] = ff2(W1[0], L, ff2(W1[1], V, ff2(W1[2], R, acc1[r + 1])));
                    }
                }
            } else {
                #pragma unroll
                for (int ri = 0; ri < 9; ri++) {
                    const int r = 7 + ri;          // global in row
                    const int t = ri - 1;          // local out base
                    ull L = *(const ull*)(rb + r * 40);
                    ull R = *(const ull*)(rb + r * 40 + 2);
                    ull V = *(const ull*)(rb + r * 40 + 20);
                    if (t >= 1) {
                        acc0[t - 1] = ff2(W0[6], L, ff2(W0[7], V, ff2(W0[8], R, acc0[t - 1])));
                        acc1[t - 1] = ff2(W1[6], L, ff2(W1[7], V, ff2(W1[8], R, acc1[t - 1])));
                    }
                    if (t >= 0 && t <= 7) {
                        acc0[t] = ff2(W0[3], L, ff2(W0[4], V, ff2(W0[5], R, acc0[t])));
                        acc1[t] = ff2(W1[3], L, ff2(W1[4], V, ff2(W1[5], R, acc1[t])));
                    }
                    if (t <= 6) {
                        acc0[t + 1] = ff2(W0[0], L, ff2(W0[1], V, ff2(W0[2], R, acc0[t + 1])));
                        acc1[t + 1] = ff2(W1[0], L, ff2(W1[1], V, ff2(W1[2], R, acc1[t + 1])));
                    }
                }
            }
        }
    }

    // BN + ReLU + 2x2 pool; local pooled rows 0..3 -> global h*4+j, col = cp
    #pragma unroll
    for (int k = 0; k < 2; k++) {
        const int oc = oc0 + k;
        const ull* ac = k ? acc1 : acc0;
        float inv = gam[oc] * rsqrtf(var[oc] + BN_EPS);
        float sh = (bias[oc] - mean[oc]) * inv + bet[oc];
        float* ob = g_h2 + (size_t)b * 4096 + (size_t)oc * 64 + cp;
        #pragma unroll
        for (int j = 0; j < 4; j++) {
            float2 a = upk2(ac[2 * j]);
            float2 c = upk2(ac[2 * j + 1]);
            float v00 = fmaxf(fmaf(a.x, inv, sh), 0.f);
            float v01 = fmaxf(fmaf(a.y, inv, sh), 0.f);
            float v10 = fmaxf(fmaf(c.x, inv, sh), 0.f);
            float v11 = fmaxf(fmaf(c.y, inv, sh), 0.f);
            ob[(h * 4 + j) * 8] = fmaxf(fmaxf(v00, v01), fmaxf(v10, v11));
        }
    }
}

// =============================================================================
// Stage 3: conv(64->128) + BN + ReLU + pool + avgpool. grid=B*2, block=128
// (4 warps x 16 oc). Lane = ocg(8) x cp(4); 2 oc/thread, all 8 rows.
// Input dual-copy rows (stride 20). Packed weights staged into smem in 16
// sub-stages of 4 ic (stride 37 ull, bank-clean); mainloop = LDS.64 only.
// =============================================================================
__global__ __launch_bounds__(128) void conv3_kernel(
    const float* __restrict__ bias,
    const float* __restrict__ gam,
    const float* __restrict__ bet,
    const float* __restrict__ mean,
    const float* __restrict__ var)
{
    __shared__ float s_in[32 * 160];   // 20 KB
    __shared__ ull   s_w[64 * 37];     // 18.9 KB (stride 37: bank-clean)

    const int b = blockIdx.x >> 1;
    const int oc_base = (blockIdx.x & 1) * 64;
    const int tid = threadIdx.x;
    const int warp = tid >> 5;
    const int lane = tid & 31;
    const int cp = lane & 3;             // col pair 0..3
    const int ocg = lane >> 2;           // 0..7
    const int oc0l = warp * 16 + ocg * 2;   // local 0..62
    const int oc0 = oc_base + oc0l;

    // static borders
    for (int i = tid; i < 256; i += 128) {
        int ic = i >> 3, r = i & 7;
        s_in[ic * 160 + r * 20] = 0.f;
        s_in[ic * 160 + r * 20 + 9] = 0.f;
    }

    ull acc0[8], acc1[8];
    #pragma unroll
    for (int i = 0; i < 8; i++) { acc0[i] = 0ull; acc1[i] = 0ull; }

    for (int pass = 0; pass < 2; pass++) {
        __syncthreads();   // prior pass's s_in reads done
        {
            const float4* src = (const float4*)(g_h2 + (size_t)b * 4096 + pass * 2048);
            #pragma unroll
            for (int i = 0; i < 4; i++) {
                int idx4 = tid + i * 128;           // 0..511
                float4 v = src[idx4];
                int ic = idx4 >> 4;
                int r = (idx4 >> 1) & 7;
                int c4 = (idx4 & 1) * 4;
                float* row = &s_in[ic * 160 + r * 20];
                row[1 + c4] = v.x; row[2 + c4] = v.y;
                row[3 + c4] = v.z; row[4 + c4] = v.w;
                *(float4*)(row + 12 + c4) = v;
            }
        }

        for (int ws = 0; ws < 8; ws++) {
            __syncthreads();   // covers input staging (ws=0) and prior s_w reads
            // stage packed weights: 64 oc x 36 ull (4 ic)
            for (int i = tid; i < 64 * 36; i += 128) {
                int o = i / 36, j = i % 36;
                s_w[o * 37 + j] =
                    g_pw3[(size_t)(oc_base + o) * 576 + (pass * 32 + ws * 4) * 9 + j];
            }
            __syncthreads();

            #pragma unroll
            for (int ici = 0; ici < 4; ici++) {
                const int icl = ws * 4 + ici;     // 0..31 within pass
                const ull* w0p = &s_w[oc0l * 37 + ici * 9];
                const ull* w1p = w0p + 37;
                ull W0[9], W1[9];
                #pragma unroll
                for (int k = 0; k < 9; k++) { W0[k] = w0p[k]; W1[k] = w1p[k]; }

                const float* rb = &s_in[icl * 160 + 2 * cp];
                #pragma unroll
                for (int r = 0; r < 8; r++) {
                    ull L = *(const ull*)(rb + r * 20);
                    ull R = *(const ull*)(rb + r * 20 + 2);
                    ull V = *(const ull*)(rb + r * 20 + 12);
                    if (r >= 1) {
                        acc0[r - 1] = ff2(W0[6], L, ff2(W0[7], V, ff2(W0[8], R, acc0[r - 1])));
                        acc1[r - 1] = ff2(W1[6], L, ff2(W1[7], V, ff2(W1[8], R, acc1[r - 1])));
                    }
                    acc0[r] = ff2(W0[3], L, ff2(W0[4], V, ff2(W0[5], R, acc0[r])));
                    acc1[r] = ff2(W1[3], L, ff2(W1[4], V, ff2(W1[5], R, acc1[r])));
                    if (r <= 6) {
                        acc0[r + 1] = ff2(W0[0], L, ff2(W0[1], V, ff2(W0[2], R, acc0[r + 1])));
                        acc1[r + 1] = ff2(W1[0], L, ff2(W1[1], V, ff2(W1[2], R, acc1[r + 1])));
                    }
                }
            }
        }
    }

    // BN + ReLU + 2x2 pool + avg: thread holds 4 pooled rows x 1 pooled col (=cp)
    #pragma unroll
    for (int k = 0; k < 2; k++) {
        const int oc = oc0 + k;
        const ull* ac = k ? acc1 : acc0;
        float inv = gam[oc] * rsqrtf(var[oc] + BN_EPS);
        float sh = (bias[oc] - mean[oc]) * inv + bet[oc];
        float sum = 0.f;
        #pragma unroll
        for (int j = 0; j < 4; j++) {
            float2 a = upk2(ac[2 * j]);
            float2 c = upk2(ac[2 * j + 1]);
            float v00 = fmaxf(fmaf(a.x, inv, sh), 0.f);
            float v01 = fmaxf(fmaf(a.y, inv, sh), 0.f);
            float v10 = fmaxf(fmaf(c.x, inv, sh), 0.f);
            float v11 = fmaxf(fmaf(c.y, inv, sh), 0.f);
            sum += fmaxf(fmaxf(v00, v01), fmaxf(v10, v11));
        }
        sum += __shfl_down_sync(0xffffffffu, sum, 2, 4);
        sum += __shfl_down_sync(0xffffffffu, sum, 1, 4);
        if (cp == 0)
            g_feat[(size_t)b * 128 + oc] = sum * (1.f / 16.f);
    }
}

// =============================================================================
// Stage 4: gate (top-2 softmax) + top-2 expert MLPs, fused. (unchanged, 55us)
// =============================================================================
__global__ __launch_bounds__(256) void moe_kernel(
    const float* __restrict__ w1,   // [8,128,64]
    const float* __restrict__ b1,   // [8,64]
    const float* __restrict__ w2,   // [8,64,10]
    const float* __restrict__ b2,   // [8,10]
    const float* __restrict__ gw,   // [128,8]
    const float* __restrict__ gb,   // [8]
    float* __restrict__ out, int B)
{
    __shared__ float s_feat[8][128];
    __shared__ float s_h[8][64];
    __shared__ float s_log[8][8];

    const int warp = threadIdx.x >> 5;
    const int lane = threadIdx.x & 31;
    const int s = blockIdx.x * 8 + warp;
    if (s >= B) return;

    for (int i = lane; i < 128; i += 32) s_feat[warp][i] = g_feat[(size_t)s * 128 + i];
    __syncwarp();

    if (lane < 8) {
        float a = gb[lane];
        for (int f = 0; f < 128; f++) a += s_feat[warp][f] * gw[f * 8 + lane];
        s_log[warp][lane] = a;
    }
    __syncwarp();

    float lg[8];
    #pragma unroll
    for (int e = 0; e < 8; e++) lg[e] = s_log[warp][e];
    int i0 = 0; float v0 = lg[0];
    #pragma unroll
    for (int e = 1; e < 8; e++) if (lg[e] > v0) { v0 = lg[e]; i0 = e; }
    int i1 = -1; float v1 = -3.402823466e38f;
    #pragma unroll
    for (int e = 0; e < 8; e++) if (e != i0 && lg[e] > v1) { v1 = lg[e]; i1 = e; }
    float e1 = expf(v1 - v0);
    float invs = 1.f / (1.f + e1);
    float wts[2] = { invs, e1 * invs };
    int eidx[2] = { i0, i1 };

    float outk = 0.f;
    for (int t = 0; t < 2; t++) {
        const int e = eidx[t];
        const float* w1e = w1 + (size_t)e * 128 * 64;
        float h0 = b1[e * 64 + lane];
        float h1v = b1[e * 64 + lane + 32];
        for (int f = 0; f < 128; f++) {
            float fv = s_feat[warp][f];
            h0  += fv * w1e[f * 64 + lane];
            h1v += fv * w1e[f * 64 + lane + 32];
        }
        s_h[warp][lane] = fmaxf(h0, 0.f);
        s_h[warp][lane + 32] = fmaxf(h1v, 0.f);
        __syncwarp();
        if (lane < 10) {
            const float* w2e = w2 + e * 640;
            float o = b2[e * 10 + lane];
            for (int j = 0; j < 64; j++) o += s_h[warp][j] * w2e[j * 10 + lane];
            outk += wts[t] * o;
        }
        __syncwarp();
    }
    if (lane < 10) out[(size_t)s * 10 + lane] = outk;
}

// =============================================================================
extern "C" void kernel_launch(void* const* d_in, const int* in_sizes, int n_in,
                              void* d_out, int out_size)
{
    const float* x       = (const float*)d_in[0];
    const float* c1w     = (const float*)d_in[1];
    const float* c1b     = (const float*)d_in[2];
    const float* bn1g    = (const float*)d_in[3];
    const float* bn1b    = (const float*)d_in[4];
    const float* bn1m    = (const float*)d_in[5];
    const float* bn1v    = (const float*)d_in[6];
    const float* c2w     = (const float*)d_in[7];
    const float* c2b     = (const float*)d_in[8];
    const float* bn2g    = (const float*)d_in[9];
    const float* bn2b    = (const float*)d_in[10];
    const float* bn2m    = (const float*)d_in[11];
    const float* bn2v    = (const float*)d_in[12];
    const float* c3w     = (const float*)d_in[13];
    const float* c3b     = (const float*)d_in[14];
    const float* bn3g    = (const float*)d_in[15];
    const float* bn3b    = (const float*)d_in[16];
    const float* bn3m    = (const float*)d_in[17];
    const float* bn3v    = (const float*)d_in[18];
    const float* w1      = (const float*)d_in[19];
    const float* b1      = (const float*)d_in[20];
    const float* w2      = (const float*)d_in[21];
    const float* b2      = (const float*)d_in[22];
    const float* gate_w  = (const float*)d_in[23];
    const float* gate_b  = (const float*)d_in[24];

    int B = in_sizes[0] / (3 * 32 * 32);
    if (B > 4096) B = 4096;

    // pack kernel doubles as launch-slot shifter: profiled slot = conv3
    pack_weights<<<288, 256>>>(c2w, c3w);
    conv1_kernel<<<B, 128>>>(x, c1w, c1b, bn1g, bn1b, bn1m, bn1v);
    conv2_kernel<<<B * 4, 128>>>(c2b, bn2g, bn2b, bn2m, bn2v);
    conv3_kernel<<<B * 2, 128>>>(c3b, bn3g, bn3b, bn3m, bn3v);
    moe_kernel<<<(B + 7) / 8, 256>>>(w1, b1, w2, b2, gate_w, gate_b, (float*)d_out, B);
}